// round 3
// baseline (speedup 1.0000x reference)
#include <cuda_runtime.h>
#include <cstdint>

// Problem constants (fixed shapes from reference)
#define T_LEN 1024
#define B_SZ  512
#define D_IN  46
#define H_SZ  128
#define G3    384   // 3*H

// Packed fp32x2 FMA (FFMA2) — PTX-only path, doubles fp32 FMA throughput.
#define FMA2(acc, a, b) asm("fma.rn.f32x2 %0, %1, %2, %0;" : "+l"(acc) : "l"(a), "l"(b))

__device__ __forceinline__ float pair_sum(unsigned long long v) {
    float lo, hi;
    asm("mov.b64 {%0,%1}, %2;" : "=f"(lo), "=f"(hi) : "l"(v));
    return lo + hi;
}

// Scratch: x_proj in [T][B][3H] layout so the scan reads one contiguous
// 6KB chunk per (CTA, step). 805 MB, static __device__ (allocation-free rule).
static __device__ float g_xproj[(size_t)T_LEN * B_SZ * G3];

// ---------------------------------------------------------------------------
// Kernel 1: x_proj[t][b][g] = sum_d hist[b][t][d] * W_ih[g][d] + b_ih[g]
// Rows (b,t) flattened b-major: m = b*T + t. 256 rows per CTA, 384 threads,
// thread g keeps its W_ih row (23 fp32 pairs) in registers; x rows staged in
// smem, read as 64-bit broadcasts. FFMA2 over the K dimension.
// ---------------------------------------------------------------------------
__global__ __launch_bounds__(384) void xproj_kernel(const float* __restrict__ hist,
                                                    const float* __restrict__ W_ih,
                                                    const float* __restrict__ b_ih) {
    __shared__ float xs[256 * D_IN];  // 47104 B
    const int g = threadIdx.x;
    const int m_base = blockIdx.x * 256;

    // Cooperative contiguous copy (256*46 floats, 16B aligned: 256*184 % 16 == 0)
    {
        const float4* src = (const float4*)(hist + (size_t)m_base * D_IN);
        float4* dst = (float4*)xs;
        for (int i = g; i < 256 * D_IN / 4; i += 384) dst[i] = src[i];
    }

    // W_ih row g as 23 packed pairs (g*46*4 = g*184 bytes, 8B aligned)
    unsigned long long w[23];
#pragma unroll
    for (int k = 0; k < 23; k++)
        w[k] = *(const unsigned long long*)(W_ih + g * D_IN + 2 * k);
    const float bias = b_ih[g];
    __syncthreads();

#pragma unroll 4
    for (int m = 0; m < 256; m++) {
        const unsigned long long* xr = (const unsigned long long*)(xs + m * D_IN);
        unsigned long long acc = 0ull;  // packed (+0.f, +0.f)
#pragma unroll
        for (int k = 0; k < 23; k++) FMA2(acc, w[k], xr[k]);
        const int mm = m_base + m;
        const int b = mm >> 10;       // / T_LEN
        const int t = mm & 1023;      // % T_LEN
        g_xproj[((size_t)t * B_SZ + b) * G3 + g] = pair_sum(acc) + bias;
    }
}

// ---------------------------------------------------------------------------
// Kernel 2: sequential GRU scan. 128 CTAs x 4 batch, 384 threads (thread g
// owns gate-row g). W_hh in smem transposed to [k4][g][4] (conflict-free
// LDS.128 across lanes). Inner product via FFMA2 packed over K. Gates on
// warps 0-3 with EX2/RCP approximations. x_proj(t+1) prefetched via cp.async.
// ---------------------------------------------------------------------------
__global__ __launch_bounds__(384) void gru_scan_kernel(const float* __restrict__ W_hh,
                                                       const float* __restrict__ b_hh,
                                                       const float* __restrict__ h0,
                                                       float* __restrict__ out) {
    extern __shared__ float smem[];
    float* Wt   = smem;               // 49152 floats (192 KB): [k4][g][4]
    float* h_s  = smem + 49152;       // 4 x 128
    float* gh_s = smem + 49664;       // 384 x 4
    float* xp_s = smem + 51200;       // 2 x (4 x 384)

    const int g  = threadIdx.x;
    const int b0 = blockIdx.x * 4;

    // Stage W_hh transposed: Wt[(k4*384+gg)*4 + j] = W_hh[gg*128 + 4*k4 + j]
    for (int idx = g; idx < 384 * 32; idx += 384) {
        const int gg = idx >> 5, k4 = idx & 31;
        const float4 v = *(const float4*)(W_hh + gg * H_SZ + k4 * 4);
        *(float4*)(Wt + ((size_t)k4 * G3 + gg) * 4) = v;
    }
    for (int i = g; i < 4 * H_SZ; i += 384) h_s[i] = h0[i & (H_SZ - 1)];
    const float bhh = b_hh[g];

    // Prefetch x_proj for t = 0 (one 16B cp.async per thread = 6 KB contiguous)
    {
        const unsigned saddr = (unsigned)__cvta_generic_to_shared(xp_s + g * 4);
        const float* src = g_xproj + ((size_t)0 * B_SZ + b0) * G3 + g * 4;
        asm volatile("cp.async.cg.shared.global [%0], [%1], 16;" :: "r"(saddr), "l"(src));
        asm volatile("cp.async.commit_group;");
    }

    for (int t = 0; t < T_LEN; t++) {
        const int cur = t & 1;
        asm volatile("cp.async.wait_group 0;");
        __syncthreads();  // xp[cur] landed; init/h_s writes visible; gh_s free

        if (t + 1 < T_LEN) {
            const unsigned saddr =
                (unsigned)__cvta_generic_to_shared(xp_s + (cur ^ 1) * (4 * G3) + g * 4);
            const float* src = g_xproj + ((size_t)(t + 1) * B_SZ + b0) * G3 + g * 4;
            asm volatile("cp.async.cg.shared.global [%0], [%1], 16;" :: "r"(saddr), "l"(src));
            asm volatile("cp.async.commit_group;");
        }

        // gh[g][b] = W_hh[g,:] . h[b,:]  (packed pairs over K)
        unsigned long long a0 = 0ull, a1 = 0ull, a2 = 0ull, a3 = 0ull;
#pragma unroll
        for (int k4 = 0; k4 < 32; k4++) {
            const ulonglong2 wv  = *(const ulonglong2*)(Wt + ((size_t)k4 * G3 + g) * 4);
            const ulonglong2 h0v = *(const ulonglong2*)(h_s + 0 * H_SZ + k4 * 4);
            const ulonglong2 h1v = *(const ulonglong2*)(h_s + 1 * H_SZ + k4 * 4);
            const ulonglong2 h2v = *(const ulonglong2*)(h_s + 2 * H_SZ + k4 * 4);
            const ulonglong2 h3v = *(const ulonglong2*)(h_s + 3 * H_SZ + k4 * 4);
            FMA2(a0, wv.x, h0v.x); FMA2(a0, wv.y, h0v.y);
            FMA2(a1, wv.x, h1v.x); FMA2(a1, wv.y, h1v.y);
            FMA2(a2, wv.x, h2v.x); FMA2(a2, wv.y, h2v.y);
            FMA2(a3, wv.x, h3v.x); FMA2(a3, wv.y, h3v.y);
        }
        float4 gh;
        gh.x = pair_sum(a0) + bhh;
        gh.y = pair_sum(a1) + bhh;
        gh.z = pair_sum(a2) + bhh;
        gh.w = pair_sum(a3) + bhh;
        *(float4*)(gh_s + g * 4) = gh;
        __syncthreads();  // gh ready; all h_s reads done before combine rewrites

        if (g < H_SZ) {
            const float* xp = xp_s + cur * (4 * G3);
#pragma unroll
            for (int b = 0; b < 4; b++) {
                const float xr = xp[b * G3 + g];
                const float xz = xp[b * G3 + H_SZ + g];
                const float xn = xp[b * G3 + 2 * H_SZ + g];
                const float gr = gh_s[g * 4 + b];
                const float gz = gh_s[(H_SZ + g) * 4 + b];
                const float gn = gh_s[(2 * H_SZ + g) * 4 + b];
                const float r = __fdividef(1.f, 1.f + __expf(-(xr + gr)));
                const float z = __fdividef(1.f, 1.f + __expf(-(xz + gz)));
                const float pre = xn + r * gn;
                // tanh(x) = 1 - 2/(exp(2x)+1); saturates correctly at +/-inf
                const float n = 1.f - 2.f * __fdividef(1.f, 1.f + __expf(2.f * pre));
                const float h = h_s[b * H_SZ + g];
                h_s[b * H_SZ + g] = n + z * (h - n);
            }
        }
        // next iteration's first __syncthreads orders h_s write -> k-loop read
    }

    __syncthreads();
    for (int i = g; i < 4 * H_SZ; i += 384)
        out[(size_t)(b0 + (i >> 7)) * H_SZ + (i & (H_SZ - 1))] = h_s[i];
}

// ---------------------------------------------------------------------------
// Launch
// ---------------------------------------------------------------------------
extern "C" void kernel_launch(void* const* d_in, const int* in_sizes, int n_in,
                              void* d_out, int out_size) {
    const float* hist = (const float*)d_in[0];  // [512,1024,46]
    const float* W_ih = (const float*)d_in[1];  // [384,46]
    const float* W_hh = (const float*)d_in[2];  // [384,128]
    const float* b_ih = (const float*)d_in[3];  // [384]
    const float* b_hh = (const float*)d_in[4];  // [384]
    const float* h0   = (const float*)d_in[5];  // [1,1,128]
    float* out = (float*)d_out;                 // [512,128]

    static_assert(sizeof(unsigned long long) == 8, "");

    const int SMEM_SCAN = (49152 + 512 + 1536 + 3072) * 4;  // 217088 B
    cudaFuncSetAttribute(gru_scan_kernel,
                         cudaFuncAttributeMaxDynamicSharedMemorySize, SMEM_SCAN);

    xproj_kernel<<<(B_SZ * T_LEN) / 256, 384>>>(hist, W_ih, b_ih);
    gru_scan_kernel<<<B_SZ / 4, 384, SMEM_SCAN>>>(W_hh, b_hh, h0, out);
}

// round 5
// speedup vs baseline: 1.2097x; 1.2097x over previous
#include <cuda_runtime.h>
#include <cstdint>

#define T_LEN 1024
#define B_SZ  512
#define D_IN  46
#define H_SZ  128
#define G3    384   // 3*H

// Split of W_hh k4-chunks: k4 < K4_REG from registers, rest from smem.
#define K4_REG 20
#define K4_SMEM (32 - K4_REG)   // 12

// Packed fp32x2 FMA (FFMA2) — PTX-only, 2x fp32 FMA throughput.
#define FMA2(acc, a, b) asm("fma.rn.f32x2 %0, %1, %2, %0;" : "+l"(acc) : "l"(a), "l"(b))

__device__ __forceinline__ float pair_sum(unsigned long long v) {
    float lo, hi;
    asm("mov.b64 {%0,%1}, %2;" : "=f"(lo), "=f"(hi) : "l"(v));
    return lo + hi;
}

// x_proj scratch, [T][B][3H] so the scan reads one contiguous 6KB chunk/step/CTA.
static __device__ float g_xproj[(size_t)T_LEN * B_SZ * G3];

// ---------------------------------------------------------------------------
// Kernel 1: x_proj[t][b][g] = hist[b][t][:] . W_ih[g][:] + b_ih[g]
// 256 rows/CTA staged in smem padded to 48 floats/row -> 12 LDS.128
// broadcasts per row. W_ih row g in registers.
// ---------------------------------------------------------------------------
__global__ __launch_bounds__(384) void xproj_kernel(const float* __restrict__ hist,
                                                    const float* __restrict__ W_ih,
                                                    const float* __restrict__ b_ih) {
    __shared__ float xs[256 * 48];  // 49152 B
    const int g = threadIdx.x;
    const int m_base = blockIdx.x * 256;

    {
        const float2* src = (const float2*)(hist + (size_t)m_base * D_IN);
        for (int i = g; i < 256 * 23; i += 384) {
            const int row = i / 23, c = i - row * 23;
            *(float2*)(xs + row * 48 + 2 * c) = src[i];
        }
    }

    unsigned long long w[23];
#pragma unroll
    for (int k = 0; k < 23; k++)
        w[k] = *(const unsigned long long*)(W_ih + g * D_IN + 2 * k);
    const float bias = b_ih[g];
    __syncthreads();

#pragma unroll 2
    for (int m = 0; m < 256; m++) {
        const ulonglong2* xr = (const ulonglong2*)(xs + m * 48);  // 192B-aligned
        ulonglong2 xv[12];
#pragma unroll
        for (int i = 0; i < 12; i++) xv[i] = xr[i];
        unsigned long long acc = 0ull;
#pragma unroll
        for (int i = 0; i < 12; i++) {
            FMA2(acc, w[2 * i], xv[i].x);
            if (2 * i + 1 < 23) FMA2(acc, w[2 * i + 1], xv[i].y);
        }
        const int mm = m_base + m;
        const int b = mm >> 10, t = mm & 1023;
        g_xproj[((size_t)t * B_SZ + b) * G3 + g] = pair_sum(acc) + bias;
    }
}

// ---------------------------------------------------------------------------
// Kernel 2: GRU scan. 128 CTAs x 4 batch, 384 threads. Thread g owns gate
// row g: k4<20 of W_hh in registers (80 regs), k4 in [20,32) in smem with
// conflict-free [k4][g][4] layout (one LDS.128 each). h broadcast LDS.128.
// Combine distributed over all 384 threads. cp.async double-buffered xp.
// ---------------------------------------------------------------------------
__global__ __launch_bounds__(384, 1) void gru_scan_kernel(const float* __restrict__ W_hh,
                                                          const float* __restrict__ b_hh,
                                                          const float* __restrict__ h0,
                                                          float* __restrict__ out) {
    extern __shared__ float smem[];
    float* Wt   = smem;                     // K4_SMEM*384*4 = 18432 floats (72 KB)
    float* h_s  = smem + 18432;             // 4*128          [b][g]
    float* gh_s = smem + 18944;             // 4*384          [b][g3]
    float* xp_s = smem + 20480;             // 2*4*384        [buf][b][g3]

    const int g  = threadIdx.x;
    const int b0 = blockIdx.x * 4;

    // W_hh row g, first K4_REG chunks -> 40 packed pairs in registers.
    unsigned long long W[2 * K4_REG];
#pragma unroll
    for (int k = 0; k < 2 * K4_REG; k++)
        W[k] = *(const unsigned long long*)(W_hh + (size_t)g * H_SZ + 2 * k);

    // Remaining chunks -> smem transposed: Wt[((k4-20)*384+gg)*4+j]
    for (int idx = g; idx < G3 * K4_SMEM; idx += 384) {
        const int gg = idx / K4_SMEM, k4r = idx - gg * K4_SMEM;
        const float4 v = *(const float4*)(W_hh + (size_t)gg * H_SZ + (K4_REG + k4r) * 4);
        *(float4*)(Wt + ((size_t)k4r * G3 + gg) * 4) = v;
    }
    for (int i = g; i < 4 * H_SZ; i += 384) h_s[i] = h0[i & (H_SZ - 1)];
    const float bhh = b_hh[g];

    // Prefetch x_proj for t=0 (16B/thread = 6KB contiguous per CTA).
    {
        const unsigned saddr = (unsigned)__cvta_generic_to_shared(xp_s + g * 4);
        const float* src = g_xproj + ((size_t)0 * B_SZ + b0) * G3 + g * 4;
        asm volatile("cp.async.cg.shared.global [%0], [%1], 16;" :: "r"(saddr), "l"(src));
        asm volatile("cp.async.commit_group;");
    }

    for (int t = 0; t < T_LEN; t++) {
        const int cur = t & 1;
        asm volatile("cp.async.wait_group 0;");
        __syncthreads();  // xp[cur] landed; previous combine's h_s writes visible

        if (t + 1 < T_LEN) {
            const unsigned saddr =
                (unsigned)__cvta_generic_to_shared(xp_s + (cur ^ 1) * (4 * G3) + g * 4);
            const float* src = g_xproj + ((size_t)(t + 1) * B_SZ + b0) * G3 + g * 4;
            asm volatile("cp.async.cg.shared.global [%0], [%1], 16;" :: "r"(saddr), "l"(src));
            asm volatile("cp.async.commit_group;");
        }

        // gh[b][g] = W_hh[g,:] . h[b,:]
        unsigned long long a0 = 0ull, a1 = 0ull, a2 = 0ull, a3 = 0ull;
#pragma unroll
        for (int k4 = 0; k4 < K4_REG; k4++) {
            const ulonglong2 h0v = *(const ulonglong2*)(h_s + 0 * H_SZ + k4 * 4);
            const ulonglong2 h1v = *(const ulonglong2*)(h_s + 1 * H_SZ + k4 * 4);
            const ulonglong2 h2v = *(const ulonglong2*)(h_s + 2 * H_SZ + k4 * 4);
            const ulonglong2 h3v = *(const ulonglong2*)(h_s + 3 * H_SZ + k4 * 4);
            FMA2(a0, W[2 * k4], h0v.x); FMA2(a0, W[2 * k4 + 1], h0v.y);
            FMA2(a1, W[2 * k4], h1v.x); FMA2(a1, W[2 * k4 + 1], h1v.y);
            FMA2(a2, W[2 * k4], h2v.x); FMA2(a2, W[2 * k4 + 1], h2v.y);
            FMA2(a3, W[2 * k4], h3v.x); FMA2(a3, W[2 * k4 + 1], h3v.y);
        }
#pragma unroll
        for (int k4r = 0; k4r < K4_SMEM; k4r++) {
            const int k4 = K4_REG + k4r;
            const ulonglong2 wv  = *(const ulonglong2*)(Wt + ((size_t)k4r * G3 + g) * 4);
            const ulonglong2 h0v = *(const ulonglong2*)(h_s + 0 * H_SZ + k4 * 4);
            const ulonglong2 h1v = *(const ulonglong2*)(h_s + 1 * H_SZ + k4 * 4);
            const ulonglong2 h2v = *(const ulonglong2*)(h_s + 2 * H_SZ + k4 * 4);
            const ulonglong2 h3v = *(const ulonglong2*)(h_s + 3 * H_SZ + k4 * 4);
            FMA2(a0, wv.x, h0v.x); FMA2(a0, wv.y, h0v.y);
            FMA2(a1, wv.x, h1v.x); FMA2(a1, wv.y, h1v.y);
            FMA2(a2, wv.x, h2v.x); FMA2(a2, wv.y, h2v.y);
            FMA2(a3, wv.x, h3v.x); FMA2(a3, wv.y, h3v.y);
        }
        gh_s[0 * G3 + g] = pair_sum(a0) + bhh;
        gh_s[1 * G3 + g] = pair_sum(a1) + bhh;
        gh_s[2 * G3 + g] = pair_sum(a2) + bhh;
        gh_s[3 * G3 + g] = pair_sum(a3) + bhh;
        __syncthreads();  // gh ready; all h_s k-loop reads done

        // Combine: 512 (b,gate-idx) tasks over 384 threads; conflict-free.
        const float* xp = xp_s + cur * (4 * G3);
        {
            const int b1 = g >> 7, g1 = g & (H_SZ - 1);
            const int rounds = (g < H_SZ) ? 2 : 1;
            for (int r = 0; r < rounds; r++) {
                const int b = (r == 0) ? b1 : 3;
                const float xr = xp[b * G3 + g1];
                const float xz = xp[b * G3 + H_SZ + g1];
                const float xn = xp[b * G3 + 2 * H_SZ + g1];
                const float gr = gh_s[b * G3 + g1];
                const float gz = gh_s[b * G3 + H_SZ + g1];
                const float gn = gh_s[b * G3 + 2 * H_SZ + g1];
                const float rr = __fdividef(1.f, 1.f + __expf(-(xr + gr)));
                const float zz = __fdividef(1.f, 1.f + __expf(-(xz + gz)));
                const float pre = xn + rr * gn;
                // tanh(x) = 1 - 2/(exp(2x)+1); saturates correctly
                const float nn = 1.f - 2.f * __fdividef(1.f, 1.f + __expf(2.f * pre));
                const float h = h_s[b * H_SZ + g1];
                h_s[b * H_SZ + g1] = nn + zz * (h - nn);
            }
        }
        // next iteration's first __syncthreads orders h_s writes -> k-loop reads
    }

    __syncthreads();
    for (int i = g; i < 4 * H_SZ; i += 384)
        out[(size_t)(b0 + (i >> 7)) * H_SZ + (i & (H_SZ - 1))] = h_s[i];
}

extern "C" void kernel_launch(void* const* d_in, const int* in_sizes, int n_in,
                              void* d_out, int out_size) {
    const float* hist = (const float*)d_in[0];  // [512,1024,46]
    const float* W_ih = (const float*)d_in[1];  // [384,46]
    const float* W_hh = (const float*)d_in[2];  // [384,128]
    const float* b_ih = (const float*)d_in[3];  // [384]
    const float* b_hh = (const float*)d_in[4];  // [384]
    const float* h0   = (const float*)d_in[5];  // [1,1,128]
    float* out = (float*)d_out;                 // [512,128]

    const int SMEM_SCAN = (18432 + 512 + 1536 + 3072) * 4;  // 94208 B
    cudaFuncSetAttribute(gru_scan_kernel,
                         cudaFuncAttributeMaxDynamicSharedMemorySize, SMEM_SCAN);

    xproj_kernel<<<(B_SZ * T_LEN) / 256, 384>>>(hist, W_ih, b_ih);
    gru_scan_kernel<<<B_SZ / 4, 384, SMEM_SCAN>>>(W_hh, b_hh, h0, out);
}

// round 6
// speedup vs baseline: 1.5536x; 1.2842x over previous
#include <cuda_runtime.h>
#include <cstdint>

#define T_LEN 1024
#define B_SZ  512
#define D_IN  46
#define H_SZ  128
#define G3    384   // 3*H

// K-split scan: per gate row, kk<KK_REG chunks (of 4 floats) from registers,
// remaining KK_SMEM chunks from smem.  Row K-half = 16 chunks.
#define KK_REG  10
#define KK_SMEM 6

// Packed fp32x2 FMA (FFMA2) — PTX-only, 2x fp32 FMA throughput.
#define FMA2(acc, a, b) asm("fma.rn.f32x2 %0, %1, %2, %0;" : "+l"(acc) : "l"(a), "l"(b))

__device__ __forceinline__ float pair_sum(unsigned long long v) {
    float lo, hi;
    asm("mov.b64 {%0,%1}, %2;" : "=f"(lo), "=f"(hi) : "l"(v));
    return lo + hi;
}

// x_proj scratch, [T][B][3H]: scan reads one contiguous 6KB chunk/step/CTA.
static __device__ float g_xproj[(size_t)T_LEN * B_SZ * G3];

// ---------------------------------------------------------------------------
// Kernel 1: x_proj[t][b][g] = hist[b][t][:] . W_ih[g][:] + b_ih[g]
// ---------------------------------------------------------------------------
__global__ __launch_bounds__(384) void xproj_kernel(const float* __restrict__ hist,
                                                    const float* __restrict__ W_ih,
                                                    const float* __restrict__ b_ih) {
    __shared__ float xs[256 * 48];  // rows padded to 48 -> 12 LDS.128 broadcasts
    const int g = threadIdx.x;
    const int m_base = blockIdx.x * 256;

    {
        const float2* src = (const float2*)(hist + (size_t)m_base * D_IN);
        for (int i = g; i < 256 * 23; i += 384) {
            const int row = i / 23, c = i - row * 23;
            *(float2*)(xs + row * 48 + 2 * c) = src[i];
        }
    }

    unsigned long long w[23];
#pragma unroll
    for (int k = 0; k < 23; k++)
        w[k] = *(const unsigned long long*)(W_ih + g * D_IN + 2 * k);
    const float bias = b_ih[g];
    __syncthreads();

#pragma unroll 2
    for (int m = 0; m < 256; m++) {
        const ulonglong2* xr = (const ulonglong2*)(xs + m * 48);
        ulonglong2 xv[12];
#pragma unroll
        for (int i = 0; i < 12; i++) xv[i] = xr[i];
        unsigned long long acc = 0ull;
#pragma unroll
        for (int i = 0; i < 12; i++) {
            FMA2(acc, w[2 * i], xv[i].x);
            if (2 * i + 1 < 23) FMA2(acc, w[2 * i + 1], xv[i].y);
        }
        const int mm = m_base + m;
        const int b = mm >> 10, t = mm & 1023;
        g_xproj[((size_t)t * B_SZ + b) * G3 + g] = pair_sum(acc) + bias;
    }
}

// ---------------------------------------------------------------------------
// Kernel 2: GRU scan, K-split layout.
// 384 threads: warps 0-5 own K in [0,64), warps 6-11 own K in [64,128).
// Thread u within a half computes gate rows (2u, 2u+1) -> each 16B h
// broadcast feeds 4 FFMA2 (2 rows) instead of 2.  Partial dot products are
// reduced through smem gh_part[khalf][b][row] and summed in the combine.
// ---------------------------------------------------------------------------
__global__ __launch_bounds__(384, 1) void gru_scan_kernel(const float* __restrict__ W_hh,
                                                          const float* __restrict__ b_hh,
                                                          const float* __restrict__ h0,
                                                          float* __restrict__ out) {
    extern __shared__ float smem[];
    float4* Ws4  = (float4*)smem;        // [2][KK_SMEM][2 rows][192] float4 = 18432 f
    float*  h_s  = smem + 18432;         // [b][g1]                     512 f
    float*  ghp  = smem + 18944;         // [khalf][b][row]             3072 f
    float*  xp_s = smem + 22016;         // [buf][b][g3]                3072 f
    // total 25088 floats = 100352 B

    const int t  = threadIdx.x;
    const int kh = (t >= 192) ? 1 : 0;   // warp-uniform (warps 0-5 vs 6-11)
    const int u  = t - 192 * kh;         // 0..191 ; rows 2u, 2u+1
    const int b0 = blockIdx.x * 4;

    // Register W: rows 2u,2u+1, k in [64*kh, 64*kh + 4*KK_REG)
    unsigned long long Wr[2][2 * KK_REG];
#pragma unroll
    for (int r = 0; r < 2; r++)
#pragma unroll
        for (int p = 0; p < 2 * KK_REG; p++)
            Wr[r][p] = *(const unsigned long long*)(W_hh + (size_t)(2 * u + r) * H_SZ +
                                                    64 * kh + 2 * p);

    // Smem W: Ws4[((khh*KK_SMEM + kr)*2 + j)*192 + uu] =
    //         W_hh[2uu+j][64*khh + (KK_REG+kr)*4 .. +4)
    for (int idx = t; idx < 2 * KK_SMEM * 2 * 192; idx += 384) {
        const int uu = idx % 192;
        int rest = idx / 192;
        const int j = rest & 1; rest >>= 1;
        const int kr = rest % KK_SMEM;
        const int khh = rest / KK_SMEM;
        Ws4[idx] = *(const float4*)(W_hh + (size_t)(2 * uu + j) * H_SZ +
                                    64 * khh + (KK_REG + kr) * 4);
    }
    for (int i = t; i < 4 * H_SZ; i += 384) h_s[i] = h0[i & (H_SZ - 1)];
    const float bh0 = b_hh[2 * u];
    const float bh1 = b_hh[2 * u + 1];

    // Prefetch x_proj for t=0 (16B/thread = 6KB contiguous per CTA).
    {
        const unsigned saddr = (unsigned)__cvta_generic_to_shared(xp_s + t * 4);
        const float* src = g_xproj + ((size_t)0 * B_SZ + b0) * G3 + t * 4;
        asm volatile("cp.async.cg.shared.global [%0], [%1], 16;" :: "r"(saddr), "l"(src));
        asm volatile("cp.async.commit_group;");
    }

    const float4* wsb = Ws4 + (size_t)kh * KK_SMEM * 2 * 192;

    for (int step = 0; step < T_LEN; step++) {
        const int cur = step & 1;
        asm volatile("cp.async.wait_group 0;");
        __syncthreads();  // xp[cur] landed; previous combine h_s writes visible

        if (step + 1 < T_LEN) {
            const unsigned saddr =
                (unsigned)__cvta_generic_to_shared(xp_s + (cur ^ 1) * (4 * G3) + t * 4);
            const float* src = g_xproj + ((size_t)(step + 1) * B_SZ + b0) * G3 + t * 4;
            asm volatile("cp.async.cg.shared.global [%0], [%1], 16;" :: "r"(saddr), "l"(src));
            asm volatile("cp.async.commit_group;");
        }

        // Partial dot products: rows (2u, 2u+1) over this thread's K-half.
        unsigned long long acc[2][4] = {{0ull,0ull,0ull,0ull},{0ull,0ull,0ull,0ull}};
        const float* hb = h_s + 64 * kh;
#pragma unroll
        for (int kk = 0; kk < KK_REG; kk++) {
#pragma unroll
            for (int b = 0; b < 4; b++) {
                const ulonglong2 hv = *(const ulonglong2*)(hb + b * H_SZ + 4 * kk);
                FMA2(acc[0][b], Wr[0][2 * kk],     hv.x);
                FMA2(acc[0][b], Wr[0][2 * kk + 1], hv.y);
                FMA2(acc[1][b], Wr[1][2 * kk],     hv.x);
                FMA2(acc[1][b], Wr[1][2 * kk + 1], hv.y);
            }
        }
#pragma unroll
        for (int kr = 0; kr < KK_SMEM; kr++) {
            const ulonglong2 w0 = *(const ulonglong2*)(wsb + (2 * kr + 0) * 192 + u);
            const ulonglong2 w1 = *(const ulonglong2*)(wsb + (2 * kr + 1) * 192 + u);
#pragma unroll
            for (int b = 0; b < 4; b++) {
                const ulonglong2 hv =
                    *(const ulonglong2*)(hb + b * H_SZ + 4 * (KK_REG + kr));
                FMA2(acc[0][b], w0.x, hv.x); FMA2(acc[0][b], w0.y, hv.y);
                FMA2(acc[1][b], w1.x, hv.x); FMA2(acc[1][b], w1.y, hv.y);
            }
        }
        // Store partials (bias folded into lo half). STS.64, conflict-free.
#pragma unroll
        for (int b = 0; b < 4; b++) {
            float s0 = pair_sum(acc[0][b]);
            float s1 = pair_sum(acc[1][b]);
            if (kh == 0) { s0 += bh0; s1 += bh1; }
            *(float2*)(ghp + (kh * 4 + b) * G3 + 2 * u) = make_float2(s0, s1);
        }
        __syncthreads();  // partials ready; h_s k-loop reads done

        // Combine: 512 (b, hidden-idx) tasks over 384 threads.
        const float* xp = xp_s + cur * (4 * G3);
        {
            const int b1 = t >> 7, g1 = t & (H_SZ - 1);
            const int rounds = (t < H_SZ) ? 2 : 1;
            for (int r = 0; r < rounds; r++) {
                const int b = (r == 0) ? b1 : 3;
                const float* plo = ghp + b * G3;            // khalf 0
                const float* phi = ghp + (4 + b) * G3;      // khalf 1
                const float gr = plo[g1]            + phi[g1];
                const float gz = plo[H_SZ + g1]     + phi[H_SZ + g1];
                const float gn = plo[2 * H_SZ + g1] + phi[2 * H_SZ + g1];
                const float xr = xp[b * G3 + g1];
                const float xz = xp[b * G3 + H_SZ + g1];
                const float xn = xp[b * G3 + 2 * H_SZ + g1];
                const float rr = __fdividef(1.f, 1.f + __expf(-(xr + gr)));
                const float zz = __fdividef(1.f, 1.f + __expf(-(xz + gz)));
                const float pre = xn + rr * gn;
                // tanh(x) = 1 - 2/(exp(2x)+1); saturates correctly
                const float nn = 1.f - 2.f * __fdividef(1.f, 1.f + __expf(2.f * pre));
                const float h = h_s[b * H_SZ + g1];
                h_s[b * H_SZ + g1] = nn + zz * (h - nn);
            }
        }
        // next iteration's first __syncthreads orders h_s writes -> k-loop reads
    }

    __syncthreads();
    for (int i = t; i < 4 * H_SZ; i += 384)
        out[(size_t)(b0 + (i >> 7)) * H_SZ + (i & (H_SZ - 1))] = h_s[i];
}

extern "C" void kernel_launch(void* const* d_in, const int* in_sizes, int n_in,
                              void* d_out, int out_size) {
    const float* hist = (const float*)d_in[0];  // [512,1024,46]
    const float* W_ih = (const float*)d_in[1];  // [384,46]
    const float* W_hh = (const float*)d_in[2];  // [384,128]
    const float* b_ih = (const float*)d_in[3];  // [384]
    const float* b_hh = (const float*)d_in[4];  // [384]
    const float* h0   = (const float*)d_in[5];  // [1,1,128]
    float* out = (float*)d_out;                 // [512,128]

    const int SMEM_SCAN = 25088 * 4;  // 100352 B
    cudaFuncSetAttribute(gru_scan_kernel,
                         cudaFuncAttributeMaxDynamicSharedMemorySize, SMEM_SCAN);

    xproj_kernel<<<(B_SZ * T_LEN) / 256, 384>>>(hist, W_ih, b_ih);
    gru_scan_kernel<<<B_SZ / 4, 384, SMEM_SCAN>>>(W_hh, b_hh, h0, out);
}

// round 7
// speedup vs baseline: 1.5961x; 1.0274x over previous
#include <cuda_runtime.h>
#include <cstdint>

#define T_LEN 1024
#define B_SZ  512
#define D_IN  46
#define H_SZ  128
#define G3    384   // 3*H

// Scan decomposition: 512 threads = 4 K-quarter groups x 128 threads.
// Thread u in a group owns gate rows 3u, 3u+1, 3u+2 over K-slice [32*kq, 32*kq+32).
// Per row-slice (8 chunks of 4 floats): KC_REG chunks from registers, KC_SMEM from smem.
#define KC_REG  5
#define KC_SMEM 3

// Packed fp32x2 FMA (FFMA2) — PTX-only, 2x fp32 FMA throughput.
#define FMA2(acc, a, b) asm("fma.rn.f32x2 %0, %1, %2, %0;" : "+l"(acc) : "l"(a), "l"(b))

__device__ __forceinline__ float pair_sum(unsigned long long v) {
    float lo, hi;
    asm("mov.b64 {%0,%1}, %2;" : "=f"(lo), "=f"(hi) : "l"(v));
    return lo + hi;
}

// x_proj scratch, [T][B][3H]: scan reads one contiguous 6KB chunk/step/CTA.
static __device__ float g_xproj[(size_t)T_LEN * B_SZ * G3];

// ---------------------------------------------------------------------------
// Kernel 1: x_proj[t][b][g] = hist[b][t][:] . W_ih[g][:] + b_ih[g]
// (unchanged from R6 — it was not the bottleneck this round)
// ---------------------------------------------------------------------------
__global__ __launch_bounds__(384) void xproj_kernel(const float* __restrict__ hist,
                                                    const float* __restrict__ W_ih,
                                                    const float* __restrict__ b_ih) {
    __shared__ float xs[256 * 48];  // rows padded to 48 -> 12 LDS.128 broadcasts
    const int g = threadIdx.x;
    const int m_base = blockIdx.x * 256;

    {
        const float2* src = (const float2*)(hist + (size_t)m_base * D_IN);
        for (int i = g; i < 256 * 23; i += 384) {
            const int row = i / 23, c = i - row * 23;
            *(float2*)(xs + row * 48 + 2 * c) = src[i];
        }
    }

    unsigned long long w[23];
#pragma unroll
    for (int k = 0; k < 23; k++)
        w[k] = *(const unsigned long long*)(W_ih + g * D_IN + 2 * k);
    const float bias = b_ih[g];
    __syncthreads();

#pragma unroll 2
    for (int m = 0; m < 256; m++) {
        const ulonglong2* xr = (const ulonglong2*)(xs + m * 48);
        ulonglong2 xv[12];
#pragma unroll
        for (int i = 0; i < 12; i++) xv[i] = xr[i];
        unsigned long long acc = 0ull;
#pragma unroll
        for (int i = 0; i < 12; i++) {
            FMA2(acc, w[2 * i], xv[i].x);
            if (2 * i + 1 < 23) FMA2(acc, w[2 * i + 1], xv[i].y);
        }
        const int mm = m_base + m;
        const int b = mm >> 10, t = mm & 1023;
        g_xproj[((size_t)t * B_SZ + b) * G3 + g] = pair_sum(acc) + bias;
    }
}

// ---------------------------------------------------------------------------
// Kernel 2: GRU scan. 512 threads, K quartered (warps 0-3: kq=0, ... 12-15: kq=3).
// Thread u owns rows 3u..3u+2; partials reduced via ghp[kq][b][row]; combine
// is exactly one task per thread.
// ---------------------------------------------------------------------------
__global__ __launch_bounds__(512, 1) void gru_scan_kernel(const float* __restrict__ W_hh,
                                                          const float* __restrict__ b_hh,
                                                          const float* __restrict__ h0,
                                                          float* __restrict__ out) {
    extern __shared__ float smem[];
    float4* Ws4  = (float4*)smem;        // [kq][kr][j][u] float4 = 4*3*3*128 = 4608 f4
    float*  h_s  = smem + 18432;         // [b][g1]              512 f
    float*  ghp  = smem + 18944;         // [kq][b][row]         4*4*384 = 6144 f
    float*  xp_s = smem + 25088;         // [buf][b][g3]         3072 f
    // total 28160 floats = 112640 B

    const int t  = threadIdx.x;
    const int kq = t >> 7;               // warp-uniform K-quarter
    const int u  = t & 127;              // rows 3u..3u+2
    const int b0 = blockIdx.x * 4;

    // Register W: rows 3u+j, k in [32*kq, 32*kq + 4*KC_REG) -> 10 pairs/row.
    unsigned long long Wr[3][2 * KC_REG];
#pragma unroll
    for (int j = 0; j < 3; j++)
#pragma unroll
        for (int p = 0; p < 2 * KC_REG; p++)
            Wr[j][p] = *(const unsigned long long*)(W_hh + (size_t)(3 * u + j) * H_SZ +
                                                    32 * kq + 2 * p);

    // Smem W: Ws4[((kqq*3 + kr)*3 + j)*128 + uu] = W_hh[3uu+j][32kqq + (KC_REG+kr)*4 ..)
    for (int idx = t; idx < 4 * 3 * 3 * 128; idx += 512) {
        const int uu = idx & 127;
        int rest = idx >> 7;
        const int j = rest % 3; rest /= 3;
        const int kr = rest % 3;
        const int kqq = rest / 3;
        Ws4[idx] = *(const float4*)(W_hh + (size_t)(3 * uu + j) * H_SZ +
                                    32 * kqq + (KC_REG + kr) * 4);
    }
    for (int i = t; i < 4 * H_SZ; i += 512) h_s[i] = h0[i & (H_SZ - 1)];
    float bh[3];
#pragma unroll
    for (int j = 0; j < 3; j++) bh[j] = b_hh[3 * u + j];

    // Prefetch x_proj for t=0 (1536 floats = 384 x 16B; threads t<384 issue).
    if (t < 384) {
        const unsigned saddr = (unsigned)__cvta_generic_to_shared(xp_s + t * 4);
        const float* src = g_xproj + ((size_t)0 * B_SZ + b0) * G3 + t * 4;
        asm volatile("cp.async.cg.shared.global [%0], [%1], 16;" :: "r"(saddr), "l"(src));
    }
    asm volatile("cp.async.commit_group;");

    const float4* wsb = Ws4 + (size_t)kq * 3 * 3 * 128;

    for (int step = 0; step < T_LEN; step++) {
        const int cur = step & 1;
        asm volatile("cp.async.wait_group 0;");
        __syncthreads();  // xp[cur] landed; previous combine h_s writes visible

        if (step + 1 < T_LEN) {
            if (t < 384) {
                const unsigned saddr =
                    (unsigned)__cvta_generic_to_shared(xp_s + (cur ^ 1) * (4 * G3) + t * 4);
                const float* src = g_xproj + ((size_t)(step + 1) * B_SZ + b0) * G3 + t * 4;
                asm volatile("cp.async.cg.shared.global [%0], [%1], 16;"
                             :: "r"(saddr), "l"(src));
            }
            asm volatile("cp.async.commit_group;");
        }

        // Partial dot products: rows 3u..3u+2 over K-quarter kq.
        unsigned long long acc[3][4];
#pragma unroll
        for (int j = 0; j < 3; j++)
#pragma unroll
            for (int b = 0; b < 4; b++) acc[j][b] = 0ull;

        const float* hb = h_s + 32 * kq;
#pragma unroll
        for (int kk = 0; kk < KC_REG; kk++) {
#pragma unroll
            for (int b = 0; b < 4; b++) {
                const ulonglong2 hv = *(const ulonglong2*)(hb + b * H_SZ + 4 * kk);
                FMA2(acc[0][b], Wr[0][2 * kk], hv.x); FMA2(acc[0][b], Wr[0][2 * kk + 1], hv.y);
                FMA2(acc[1][b], Wr[1][2 * kk], hv.x); FMA2(acc[1][b], Wr[1][2 * kk + 1], hv.y);
                FMA2(acc[2][b], Wr[2][2 * kk], hv.x); FMA2(acc[2][b], Wr[2][2 * kk + 1], hv.y);
            }
        }
#pragma unroll
        for (int kr = 0; kr < KC_SMEM; kr++) {
            const ulonglong2 w0 = *(const ulonglong2*)(wsb + ((kr * 3) + 0) * 128 + u);
            const ulonglong2 w1 = *(const ulonglong2*)(wsb + ((kr * 3) + 1) * 128 + u);
            const ulonglong2 w2 = *(const ulonglong2*)(wsb + ((kr * 3) + 2) * 128 + u);
#pragma unroll
            for (int b = 0; b < 4; b++) {
                const ulonglong2 hv =
                    *(const ulonglong2*)(hb + b * H_SZ + 4 * (KC_REG + kr));
                FMA2(acc[0][b], w0.x, hv.x); FMA2(acc[0][b], w0.y, hv.y);
                FMA2(acc[1][b], w1.x, hv.x); FMA2(acc[1][b], w1.y, hv.y);
                FMA2(acc[2][b], w2.x, hv.x); FMA2(acc[2][b], w2.y, hv.y);
            }
        }
        // Store partials; bias folded into kq==0 (warp-uniform branch).
#pragma unroll
        for (int b = 0; b < 4; b++) {
            float* dst = ghp + (kq * 4 + b) * G3 + 3 * u;
#pragma unroll
            for (int j = 0; j < 3; j++) {
                float s = pair_sum(acc[j][b]);
                if (kq == 0) s += bh[j];
                dst[j] = s;
            }
        }
        __syncthreads();  // partials ready; h_s k-loop reads done

        // Combine: exactly one (b, hidden-idx) task per thread.
        {
            const float* xp = xp_s + cur * (4 * G3);
            const int b = t >> 7, g1 = t & (H_SZ - 1);
            const float* p0 = ghp + (0 * 4 + b) * G3;
            const float* p1 = ghp + (1 * 4 + b) * G3;
            const float* p2 = ghp + (2 * 4 + b) * G3;
            const float* p3 = ghp + (3 * 4 + b) * G3;
            const float gr = p0[g1] + p1[g1] + p2[g1] + p3[g1];
            const float gz = p0[H_SZ + g1] + p1[H_SZ + g1] + p2[H_SZ + g1] + p3[H_SZ + g1];
            const float gn = p0[2 * H_SZ + g1] + p1[2 * H_SZ + g1] +
                             p2[2 * H_SZ + g1] + p3[2 * H_SZ + g1];
            const float xr = xp[b * G3 + g1];
            const float xz = xp[b * G3 + H_SZ + g1];
            const float xn = xp[b * G3 + 2 * H_SZ + g1];
            const float rr = __fdividef(1.f, 1.f + __expf(-(xr + gr)));
            const float zz = __fdividef(1.f, 1.f + __expf(-(xz + gz)));
            const float pre = xn + rr * gn;
            // tanh(x) = 1 - 2/(exp(2x)+1); saturates correctly
            const float nn = 1.f - 2.f * __fdividef(1.f, 1.f + __expf(2.f * pre));
            const float h = h_s[t];
            h_s[t] = nn + zz * (h - nn);
        }
        // next iteration's first __syncthreads orders h_s writes -> k-loop reads
    }

    __syncthreads();
    out[(size_t)(b0 + (t >> 7)) * H_SZ + (t & (H_SZ - 1))] = h_s[t];
}

extern "C" void kernel_launch(void* const* d_in, const int* in_sizes, int n_in,
                              void* d_out, int out_size) {
    const float* hist = (const float*)d_in[0];  // [512,1024,46]
    const float* W_ih = (const float*)d_in[1];  // [384,46]
    const float* W_hh = (const float*)d_in[2];  // [384,128]
    const float* b_ih = (const float*)d_in[3];  // [384]
    const float* b_hh = (const float*)d_in[4];  // [384]
    const float* h0   = (const float*)d_in[5];  // [1,1,128]
    float* out = (float*)d_out;                 // [512,128]

    const int SMEM_SCAN = 28160 * 4;  // 112640 B
    cudaFuncSetAttribute(gru_scan_kernel,
                         cudaFuncAttributeMaxDynamicSharedMemorySize, SMEM_SCAN);

    xproj_kernel<<<(B_SZ * T_LEN) / 256, 384>>>(hist, W_ih, b_ih);
    gru_scan_kernel<<<B_SZ / 4, 512, SMEM_SCAN>>>(W_hh, b_hh, h0, out);
}

// round 8
// speedup vs baseline: 1.7001x; 1.0652x over previous
#include <cuda_runtime.h>
#include <cstdint>

#define T_LEN 1024
#define B_SZ  512
#define D_IN  46
#define H_SZ  128
#define G3    384   // 3*H

// Scan decomposition: 512 threads = 4 K-quarter groups x 128 threads.
// Thread u in a group owns gate rows 3u..3u+2 over K-slice [32*kq, 32*kq+32).
#define KC_REG  5
#define KC_SMEM 3

// Packed fp32x2 FMA (FFMA2) — PTX-only, 2x fp32 FMA throughput.
#define FMA2(acc, a, b) asm("fma.rn.f32x2 %0, %1, %2, %0;" : "+l"(acc) : "l"(a), "l"(b))

__device__ __forceinline__ float pair_sum(unsigned long long v) {
    float lo, hi;
    asm("mov.b64 {%0,%1}, %2;" : "=f"(lo), "=f"(hi) : "l"(v));
    return lo + hi;
}

// x_proj scratch, [T][B][3H]: scan reads one contiguous 6KB chunk/step/CTA.
static __device__ float g_xproj[(size_t)T_LEN * B_SZ * G3];

// ---------------------------------------------------------------------------
// Kernel 1 (v2): x_proj[t][b][g] = hist[b][t][:] . W_ih[g][:] + b_ih[g]
// 192 threads (6 warps), 2 gates per thread (t, t+192), 128 rows per CTA.
// Halves broadcast wavefronts per row vs 12-warp version; FMA-bound.
// ---------------------------------------------------------------------------
__global__ __launch_bounds__(192, 2) void xproj_kernel(const float* __restrict__ hist,
                                                       const float* __restrict__ W_ih,
                                                       const float* __restrict__ b_ih) {
    __shared__ float xs[128 * 48];  // rows padded to 48 -> 12 LDS.128 broadcasts
    const int tid = threadIdx.x;
    const int m_base = blockIdx.x * 128;

    {   // 128 rows x 46 floats contiguous = 2944 float2
        const float2* src = (const float2*)(hist + (size_t)m_base * D_IN);
        for (int i = tid; i < 128 * 23; i += 192) {
            const int row = i / 23, c = i - row * 23;
            *(float2*)(xs + row * 48 + 2 * c) = src[i];
        }
    }

    unsigned long long w0[23], w1[23];
#pragma unroll
    for (int k = 0; k < 23; k++) {
        w0[k] = *(const unsigned long long*)(W_ih + (size_t)tid * D_IN + 2 * k);
        w1[k] = *(const unsigned long long*)(W_ih + (size_t)(tid + 192) * D_IN + 2 * k);
    }
    const float bias0 = b_ih[tid];
    const float bias1 = b_ih[tid + 192];
    __syncthreads();

#pragma unroll 2
    for (int m = 0; m < 128; m++) {
        const ulonglong2* xr = (const ulonglong2*)(xs + m * 48);
        unsigned long long a0 = 0ull, a1 = 0ull;
#pragma unroll
        for (int i = 0; i < 12; i++) {
            const ulonglong2 xv = xr[i];
            FMA2(a0, w0[2 * i], xv.x);
            FMA2(a1, w1[2 * i], xv.x);
            if (2 * i + 1 < 23) {
                FMA2(a0, w0[2 * i + 1], xv.y);
                FMA2(a1, w1[2 * i + 1], xv.y);
            }
        }
        const int mm = m_base + m;
        const int b = mm >> 10, t = mm & 1023;
        float* dst = g_xproj + ((size_t)t * B_SZ + b) * G3;
        dst[tid]       = pair_sum(a0) + bias0;
        dst[tid + 192] = pair_sum(a1) + bias1;
    }
}

// ---------------------------------------------------------------------------
// Kernel 2: GRU scan. 512 threads, K quartered (warps 0-3: kq=0, ...).
// Thread u owns rows 3u..3u+2; partials via ghp[kq][b][row]; combine is one
// task per thread with its xp/h inputs HOISTED before the second barrier.
// ---------------------------------------------------------------------------
__global__ __launch_bounds__(512, 1) void gru_scan_kernel(const float* __restrict__ W_hh,
                                                          const float* __restrict__ b_hh,
                                                          const float* __restrict__ h0,
                                                          float* __restrict__ out) {
    extern __shared__ float smem[];
    float4* Ws4  = (float4*)smem;        // [kq][kr][j][u] float4 = 4608 f4 = 18432 f
    float*  h_s  = smem + 18432;         // [b][g1]              512 f
    float*  ghp  = smem + 18944;         // [kq][b][row]         6144 f
    float*  xp_s = smem + 25088;         // [buf][b][g3]         3072 f
    // total 28160 floats = 112640 B

    const int t  = threadIdx.x;
    const int kq = t >> 7;               // warp-uniform K-quarter
    const int u  = t & 127;              // rows 3u..3u+2
    const int b0 = blockIdx.x * 4;

    unsigned long long Wr[3][2 * KC_REG];
#pragma unroll
    for (int j = 0; j < 3; j++)
#pragma unroll
        for (int p = 0; p < 2 * KC_REG; p++)
            Wr[j][p] = *(const unsigned long long*)(W_hh + (size_t)(3 * u + j) * H_SZ +
                                                    32 * kq + 2 * p);

    for (int idx = t; idx < 4 * 3 * 3 * 128; idx += 512) {
        const int uu = idx & 127;
        int rest = idx >> 7;
        const int j = rest % 3; rest /= 3;
        const int kr = rest % 3;
        const int kqq = rest / 3;
        Ws4[idx] = *(const float4*)(W_hh + (size_t)(3 * uu + j) * H_SZ +
                                    32 * kqq + (KC_REG + kr) * 4);
    }
    for (int i = t; i < 4 * H_SZ; i += 512) h_s[i] = h0[i & (H_SZ - 1)];
    float bh[3];
#pragma unroll
    for (int j = 0; j < 3; j++) bh[j] = b_hh[3 * u + j];

    if (t < 384) {
        const unsigned saddr = (unsigned)__cvta_generic_to_shared(xp_s + t * 4);
        const float* src = g_xproj + ((size_t)0 * B_SZ + b0) * G3 + t * 4;
        asm volatile("cp.async.cg.shared.global [%0], [%1], 16;" :: "r"(saddr), "l"(src));
    }
    asm volatile("cp.async.commit_group;");

    const float4* wsb = Ws4 + (size_t)kq * 3 * 3 * 128;
    const int cb = t >> 7, cg = t & (H_SZ - 1);   // combine task (b, hidden idx)

    for (int step = 0; step < T_LEN; step++) {
        const int cur = step & 1;
        asm volatile("cp.async.wait_group 0;");
        __syncthreads();  // bar A: xp[cur] landed; previous combine h_s visible

        if (step + 1 < T_LEN) {
            if (t < 384) {
                const unsigned saddr =
                    (unsigned)__cvta_generic_to_shared(xp_s + (cur ^ 1) * (4 * G3) + t * 4);
                const float* src = g_xproj + ((size_t)(step + 1) * B_SZ + b0) * G3 + t * 4;
                asm volatile("cp.async.cg.shared.global [%0], [%1], 16;"
                             :: "r"(saddr), "l"(src));
            }
            asm volatile("cp.async.commit_group;");
        }

        // Partial dot products: rows 3u..3u+2 over K-quarter kq.
        unsigned long long acc[3][4];
#pragma unroll
        for (int j = 0; j < 3; j++)
#pragma unroll
            for (int b = 0; b < 4; b++) acc[j][b] = 0ull;

        const float* hb = h_s + 32 * kq;
#pragma unroll
        for (int kk = 0; kk < KC_REG; kk++) {
#pragma unroll
            for (int b = 0; b < 4; b++) {
                const ulonglong2 hv = *(const ulonglong2*)(hb + b * H_SZ + 4 * kk);
                FMA2(acc[0][b], Wr[0][2 * kk], hv.x); FMA2(acc[0][b], Wr[0][2 * kk + 1], hv.y);
                FMA2(acc[1][b], Wr[1][2 * kk], hv.x); FMA2(acc[1][b], Wr[1][2 * kk + 1], hv.y);
                FMA2(acc[2][b], Wr[2][2 * kk], hv.x); FMA2(acc[2][b], Wr[2][2 * kk + 1], hv.y);
            }
        }
#pragma unroll
        for (int kr = 0; kr < KC_SMEM; kr++) {
            const ulonglong2 w0 = *(const ulonglong2*)(wsb + ((kr * 3) + 0) * 128 + u);
            const ulonglong2 w1 = *(const ulonglong2*)(wsb + ((kr * 3) + 1) * 128 + u);
            const ulonglong2 w2 = *(const ulonglong2*)(wsb + ((kr * 3) + 2) * 128 + u);
#pragma unroll
            for (int b = 0; b < 4; b++) {
                const ulonglong2 hv =
                    *(const ulonglong2*)(hb + b * H_SZ + 4 * (KC_REG + kr));
                FMA2(acc[0][b], w0.x, hv.x); FMA2(acc[0][b], w0.y, hv.y);
                FMA2(acc[1][b], w1.x, hv.x); FMA2(acc[1][b], w1.y, hv.y);
                FMA2(acc[2][b], w2.x, hv.x); FMA2(acc[2][b], w2.y, hv.y);
            }
        }
        // Store partials; bias folded into kq==0 (warp-uniform branch).
#pragma unroll
        for (int b = 0; b < 4; b++) {
            float* dst = ghp + (kq * 4 + b) * G3 + 3 * u;
#pragma unroll
            for (int j = 0; j < 3; j++) {
                float s = pair_sum(acc[j][b]);
                if (kq == 0) s += bh[j];
                dst[j] = s;
            }
        }

        // HOISTED combine inputs (stable since bar A): shortens post-bar-B chain.
        const float* xp = xp_s + cur * (4 * G3);
        const float xr = xp[cb * G3 + cg];
        const float xz = xp[cb * G3 + H_SZ + cg];
        const float xn = xp[cb * G3 + 2 * H_SZ + cg];
        const float hprev = h_s[t];

        __syncthreads();  // bar B: partials ready; h_s k-loop reads done

        // Combine: one (b, hidden-idx) task per thread.
        {
            const float* p0 = ghp + (0 * 4 + cb) * G3;
            const float* p1 = ghp + (1 * 4 + cb) * G3;
            const float* p2 = ghp + (2 * 4 + cb) * G3;
            const float* p3 = ghp + (3 * 4 + cb) * G3;
            const float gr = p0[cg] + p1[cg] + p2[cg] + p3[cg];
            const float gz = p0[H_SZ + cg] + p1[H_SZ + cg] + p2[H_SZ + cg] + p3[H_SZ + cg];
            const float gn = p0[2 * H_SZ + cg] + p1[2 * H_SZ + cg] +
                             p2[2 * H_SZ + cg] + p3[2 * H_SZ + cg];
            const float rr = __fdividef(1.f, 1.f + __expf(-(xr + gr)));
            const float zz = __fdividef(1.f, 1.f + __expf(-(xz + gz)));
            const float pre = xn + rr * gn;
            // tanh(x) = 1 - 2/(exp(2x)+1); saturates correctly
            const float nn = 1.f - 2.f * __fdividef(1.f, 1.f + __expf(2.f * pre));
            h_s[t] = nn + zz * (hprev - nn);
        }
        // next iteration's bar A orders h_s writes -> k-loop reads
    }

    __syncthreads();
    out[(size_t)(b0 + (t >> 7)) * H_SZ + (t & (H_SZ - 1))] = h_s[t];
}

extern "C" void kernel_launch(void* const* d_in, const int* in_sizes, int n_in,
                              void* d_out, int out_size) {
    const float* hist = (const float*)d_in[0];  // [512,1024,46]
    const float* W_ih = (const float*)d_in[1];  // [384,46]
    const float* W_hh = (const float*)d_in[2];  // [384,128]
    const float* b_ih = (const float*)d_in[3];  // [384]
    const float* b_hh = (const float*)d_in[4];  // [384]
    const float* h0   = (const float*)d_in[5];  // [1,1,128]
    float* out = (float*)d_out;                 // [512,128]

    const int SMEM_SCAN = 28160 * 4;  // 112640 B
    cudaFuncSetAttribute(gru_scan_kernel,
                         cudaFuncAttributeMaxDynamicSharedMemorySize, SMEM_SCAN);

    xproj_kernel<<<(B_SZ * T_LEN) / 128, 192>>>(hist, W_ih, b_ih);
    gru_scan_kernel<<<B_SZ / 4, 512, SMEM_SCAN>>>(W_hh, b_hh, h0, out);
}

// round 9
// speedup vs baseline: 1.7177x; 1.0103x over previous
#include <cuda_runtime.h>
#include <cstdint>

#define T_LEN 1024
#define B_SZ  512
#define D_IN  46
#define H_SZ  128
#define G3    384   // 3*H

#define KC_REG  5
#define KC_SMEM 3

#define WS4_F4_STRIDE 1154
#define OFF_HS   (WS4_F4_STRIDE * 4 * 4)   // 18464 floats
#define HS_BSTR  144
#define HS_BUF   576
#define OFF_XP   (OFF_HS + 2 * HS_BUF)     // 19616
#define XP_BSTR  392
#define XP_BUF   (4 * XP_BSTR)             // 1568
#define SMEM_F   (OFF_XP + 2 * XP_BUF)     // 22752 floats = 91008 B

#define FMA2(acc, a, b) asm("fma.rn.f32x2 %0, %1, %2, %0;" : "+l"(acc) : "l"(a), "l"(b))

__device__ __forceinline__ float pair_sum(unsigned long long v) {
    float lo, hi;
    asm("mov.b64 {%0,%1}, %2;" : "=f"(lo), "=f"(hi) : "l"(v));
    return lo + hi;
}

static __device__ float g_xproj[(size_t)T_LEN * B_SZ * G3];

__global__ __launch_bounds__(192, 2) void xproj_kernel(const float* __restrict__ hist,
                                                       const float* __restrict__ W_ih,
                                                       const float* __restrict__ b_ih) {
    __shared__ float xs[128 * 48];
    const int tid = threadIdx.x;
    const int m_base = blockIdx.x * 128;

    {
        const float2* src = (const float2*)(hist + (size_t)m_base * D_IN);
        for (int i = tid; i < 128 * 23; i += 192) {
            const int row = i / 23, c = i - row * 23;
            *(float2*)(xs + row * 48 + 2 * c) = src[i];
        }
    }

    unsigned long long w0[23], w1[23];
#pragma unroll
    for (int k = 0; k < 23; k++) {
        w0[k] = *(const unsigned long long*)(W_ih + (size_t)tid * D_IN + 2 * k);
        w1[k] = *(const unsigned long long*)(W_ih + (size_t)(tid + 192) * D_IN + 2 * k);
    }
    const float bias0 = b_ih[tid];
    const float bias1 = b_ih[tid + 192];
    __syncthreads();

#pragma unroll 2
    for (int m = 0; m < 128; m++) {
        const ulonglong2* xr = (const ulonglong2*)(xs + m * 48);
        unsigned long long a0 = 0ull, a1 = 0ull;
#pragma unroll
        for (int i = 0; i < 12; i++) {
            const ulonglong2 xv = xr[i];
            FMA2(a0, w0[2 * i], xv.x);
            FMA2(a1, w1[2 * i], xv.x);
            if (2 * i + 1 < 23) {
                FMA2(a0, w0[2 * i + 1], xv.y);
                FMA2(a1, w1[2 * i + 1], xv.y);
            }
        }
        const int mm = m_base + m;
        const int b = mm >> 10, t = mm & 1023;
        float* dst = g_xproj + ((size_t)t * B_SZ + b) * G3;
        dst[tid]       = pair_sum(a0) + bias0;
        dst[tid + 192] = pair_sum(a1) + bias1;
    }
}

__global__ __launch_bounds__(512, 1) void gru_scan_kernel(const float* __restrict__ W_hh,
                                                          const float* __restrict__ b_hh,
                                                          const float* __restrict__ h0,
                                                          float* __restrict__ out) {
    extern __shared__ float smem[];
    float4* Ws4 = (float4*)smem;
    float*  h_s = smem + OFF_HS;
    float*  xp  = smem + OFF_XP;

    const int t    = threadIdx.x;
    const int w    = t >> 5;
    const int lane = t & 31;
    const int kq   = lane >> 3;           // K-quarter; also the batch this thread combines
    const int u    = w * 8 + (lane & 7);  // hidden index 0..127

    unsigned long long Wr[3][2 * KC_REG];
#pragma unroll
    for (int j = 0; j < 3; j++)
#pragma unroll
        for (int p = 0; p < 2 * KC_REG; p++)
            Wr[j][p] = *(const unsigned long long*)(W_hh + (size_t)(j * H_SZ + u) * H_SZ +
                                                    32 * kq + 2 * p);

    for (int idx = t; idx < 4 * 9 * 128; idx += 512) {
        const int kqq = idx / 1152;
        const int within = idx - kqq * 1152;
        const int uu = within & 127;
        const int q = within >> 7;
        const int kr = q / 3, j = q - 3 * kr;
        Ws4[kqq * WS4_F4_STRIDE + within] =
            *(const float4*)(W_hh + (size_t)(j * H_SZ + uu) * H_SZ +
                             32 * kqq + (KC_REG + kr) * 4);
    }
    for (int i = t; i < 4 * H_SZ; i += 512) {
        const int b = i >> 7, g = i & 127;
        h_s[b * HS_BSTR + (g >> 5) * 36 + (g & 31)] = h0[g];
    }
    float bh[3];
#pragma unroll
    for (int j = 0; j < 3; j++) bh[j] = b_hh[j * H_SZ + u];

    const int b0 = blockIdx.x * 4;
    if (t < 384) {
        const int pb = t / 96, off = (t - pb * 96) * 4;
        const unsigned saddr =
            (unsigned)__cvta_generic_to_shared(xp + pb * XP_BSTR + off);
        const float* src = g_xproj + ((size_t)0 * B_SZ + b0 + pb) * G3 + off;
        asm volatile("cp.async.cg.shared.global [%0], [%1], 16;" :: "r"(saddr), "l"(src));
    }
    asm volatile("cp.async.commit_group;");

    const float4* wsb = Ws4 + (size_t)kq * WS4_F4_STRIDE;
    float hnew = 0.f;

    for (int step = 0; step < T_LEN; step++) {
        const int cur = step & 1, nxt = cur ^ 1;
        asm volatile("cp.async.wait_group 0;");
        __syncthreads();  // xp[cur] landed; h_s[cur] (prev combine) visible

        if (step + 1 < T_LEN) {
            if (t < 384) {
                const int pb = t / 96, off = (t - pb * 96) * 4;
                const unsigned saddr = (unsigned)__cvta_generic_to_shared(
                    xp + nxt * XP_BUF + pb * XP_BSTR + off);
                const float* src =
                    g_xproj + ((size_t)(step + 1) * B_SZ + b0 + pb) * G3 + off;
                asm volatile("cp.async.cg.shared.global [%0], [%1], 16;"
                             :: "r"(saddr), "l"(src));
            }
            asm volatile("cp.async.commit_group;");
        }

        unsigned long long acc[3][4];
#pragma unroll
        for (int j = 0; j < 3; j++)
#pragma unroll
            for (int b = 0; b < 4; b++) acc[j][b] = 0ull;

        const float* hb = h_s + cur * HS_BUF + kq * 36;
#pragma unroll
        for (int kk = 0; kk < KC_REG; kk++) {
#pragma unroll
            for (int b = 0; b < 4; b++) {
                const ulonglong2 hv = *(const ulonglong2*)(hb + b * HS_BSTR + 4 * kk);
                FMA2(acc[0][b], Wr[0][2 * kk], hv.x); FMA2(acc[0][b], Wr[0][2 * kk + 1], hv.y);
                FMA2(acc[1][b], Wr[1][2 * kk], hv.x); FMA2(acc[1][b], Wr[1][2 * kk + 1], hv.y);
                FMA2(acc[2][b], Wr[2][2 * kk], hv.x); FMA2(acc[2][b], Wr[2][2 * kk + 1], hv.y);
            }
        }
#pragma unroll
        for (int kr = 0; kr < KC_SMEM; kr++) {
            const ulonglong2 w0 = *(const ulonglong2*)(wsb + (kr * 3 + 0) * 128 + u);
            const ulonglong2 w1 = *(const ulonglong2*)(wsb + (kr * 3 + 1) * 128 + u);
            const ulonglong2 w2 = *(const ulonglong2*)(wsb + (kr * 3 + 2) * 128 + u);
#pragma unroll
            for (int b = 0; b < 4; b++) {
                const ulonglong2 hv =
                    *(const ulonglong2*)(hb + b * HS_BSTR + 4 * (KC_REG + kr));
                FMA2(acc[0][b], w0.x, hv.x); FMA2(acc[0][b], w0.y, hv.y);
                FMA2(acc[1][b], w1.x, hv.x); FMA2(acc[1][b], w1.y, hv.y);
                FMA2(acc[2][b], w2.x, hv.x); FMA2(acc[2][b], w2.y, hv.y);
            }
        }

        // Cross-kq reduction per (gate j, batch b): butterfly ^8, ^16.
        // Each replica then keeps batch b == its kq.
        float gh[3];
#pragma unroll
        for (int j = 0; j < 3; j++) {
            float keep = 0.f;
#pragma unroll
            for (int b = 0; b < 4; b++) {
                float s = pair_sum(acc[j][b]);
                s += __shfl_xor_sync(0xffffffffu, s, 8);
                s += __shfl_xor_sync(0xffffffffu, s, 16);
                if (b == kq) keep = s;
            }
            gh[j] = keep + bh[j];
        }

        // Combine for (batch kq, hidden u); write into NEXT h buffer.
        {
            const float* xb = xp + cur * XP_BUF + kq * XP_BSTR;
            const float xr = xb[u];
            const float xz = xb[H_SZ + u];
            const float xn = xb[2 * H_SZ + u];
            const float hprev = h_s[cur * HS_BUF + kq * HS_BSTR + (u >> 5) * 36 + (u & 31)];
            const float rr = __fdividef(1.f, 1.f + __expf(-(xr + gh[0])));
            const float zz = __fdividef(1.f, 1.f + __expf(-(xz + gh[1])));
            const float pre = xn + rr * gh[2];
            // tanh(x) = 1 - 2/(exp(2x)+1); saturates correctly
            const float nn = 1.f - 2.f * __fdividef(1.f, 1.f + __expf(2.f * pre));
            hnew = nn + zz * (hprev - nn);
            h_s[nxt * HS_BUF + kq * HS_BSTR + (u >> 5) * 36 + (u & 31)] = hnew;
        }
    }

    out[(size_t)(b0 + kq) * H_SZ + u] = hnew;
}

extern "C" void kernel_launch(void* const* d_in, const int* in_sizes, int n_in,
                              void* d_out, int out_size) {
    const float* hist = (const float*)d_in[0];  // [512,1024,46]
    const float* W_ih = (const float*)d_in[1];  // [384,46]
    const float* W_hh = (const float*)d_in[2];  // [384,128]
    const float* b_ih = (const float*)d_in[3];  // [384]
    const float* b_hh = (const float*)d_in[4];  // [384]
    const float* h0   = (const float*)d_in[5];  // [1,1,128]
    float* out = (float*)d_out;                 // [512,128]

    const int SMEM_SCAN = SMEM_F * 4;  // 91008 B
    cudaFuncSetAttribute(gru_scan_kernel,
                         cudaFuncAttributeMaxDynamicSharedMemorySize, SMEM_SCAN);

    xproj_kernel<<<(B_SZ * T_LEN) / 128, 192>>>(hist, W_ih, b_ih);
    gru_scan_kernel<<<B_SZ / 4, 512, SMEM_SCAN>>>(W_hh, b_hh, h0, out);
}